// round 6
// baseline (speedup 1.0000x reference)
#include <cuda_runtime.h>
#include <cuda_fp16.h>
#include <cuda_bf16.h>

// Problem constants (fixed by the reference).
#define U_CNT 100000
#define I_CNT 100000
#define N_CNT 200000           // U + I
#define L_LAYERS 3
#define ROW_F4 16              // D/4 float4 per node row (fp32 inputs)
#define ROW_H4 8               // 8 uint4 per node row (64 halves, 128B)
#define NH4   (N_CNT * ROW_H4) // 1.6M uint4 = 25.6 MB per layer buffer
#define E_MAX 6400000
#define SCAN_BLK 1024
#define SCAN_NB ((N_CNT + SCAN_BLK - 1) / SCAN_BLK)   // 196
#define DBINS 256

// val quantization: val in [0, 1/32), 14-bit fixed point in bits [18,32).
#define VAL_ENC_SCALE (32.0f * 16383.0f)
#define VAL_DEC_SCALE (1.0f / (32.0f * 16383.0f))

// Scratch (__device__ globals only — allocation-free rule).
// Steady-state invariants maintained across calls (zero-init by loader first):
//   g_deg  == 0 on entry (re-zeroed in k_scan3)
//   g_dbin == 0 on entry (re-zeroed in k_scatter)
//   g_tick == 0 on entry (re-zeroed by scan1's last block)
__device__ uint4    g_Lh[L_LAYERS + 1][NH4];   // 4 x 25.6 MB fp16 layer buffers
__device__ uint4    g_sem[NH4];                // fp16 semantic (symptom|herb) table
__device__ unsigned g_csr [E_MAX];             // packed (col | q<<18), grouped by row
__device__ int      g_rank[E_MAX];             // within-row rank of each edge
__device__ int      g_deg [N_CNT];
__device__ int      g_ptr [N_CNT + 1];
__device__ int      g_bsum[SCAN_NB];
__device__ int      g_dbin[DBINS];             // degree histogram -> cursor
__device__ int      g_order[N_CNT];            // rows in DESCENDING degree order
__device__ int      g_tick;

__device__ __forceinline__ float sigm(float x) { return 1.0f / (1.0f + __expf(-x)); }

__device__ __forceinline__ uint4 pack8(const float* x)
{
    uint4 r;
    half2 h0 = __floats2half2_rn(x[0], x[1]);
    half2 h1 = __floats2half2_rn(x[2], x[3]);
    half2 h2 = __floats2half2_rn(x[4], x[5]);
    half2 h3 = __floats2half2_rn(x[6], x[7]);
    r.x = *(unsigned*)&h0; r.y = *(unsigned*)&h1;
    r.z = *(unsigned*)&h2; r.w = *(unsigned*)&h3;
    return r;
}

__device__ __forceinline__ void unpack8(uint4 q, float* x)
{
    half2* hp = (half2*)&q;
    float2 f0 = __half22float2(hp[0]);
    float2 f1 = __half22float2(hp[1]);
    float2 f2 = __half22float2(hp[2]);
    float2 f3 = __half22float2(hp[3]);
    x[0] = f0.x; x[1] = f0.y; x[2] = f1.x; x[3] = f1.y;
    x[4] = f2.x; x[5] = f2.y; x[6] = f3.x; x[7] = f3.y;
}

__device__ __forceinline__ void acc8(float* acc, uint4 q, float v)
{
    float x[8];
    unpack8(q, x);
    #pragma unroll
    for (int k = 0; k < 8; k++) acc[k] = fmaf(v, x[k], acc[k]);
}

// ---------------------------------------------------------------------------
// Fused: layer-0 mix -> g_Lh[0] (fp16), semantic table -> g_sem (fp16),
// degree histogram AND per-edge within-row rank (the atomic's return value).
// Requires g_deg == 0 on entry (invariant).
// ---------------------------------------------------------------------------
__global__ void k_init_hist(const float4* __restrict__ ue, const float4* __restrict__ ie,
                            const float4* __restrict__ se, const float4* __restrict__ he,
                            const float*  __restrict__ ulw, const float* __restrict__ ilw,
                            const int*    __restrict__ row, int E)
{
    int i = blockIdx.x * blockDim.x + threadIdx.x;

    // degree histogram + rank capture: 4 edges per thread
    int e0 = i * 4;
    if (e0 + 3 < E) {
        int4 r4 = __ldg((const int4*)(row + e0));
        int4 k4;
        k4.x = atomicAdd(&g_deg[r4.x], 1);
        k4.y = atomicAdd(&g_deg[r4.y], 1);
        k4.z = atomicAdd(&g_deg[r4.z], 1);
        k4.w = atomicAdd(&g_deg[r4.w], 1);
        *(int4*)(g_rank + e0) = k4;
    } else if (e0 < E) {
        for (int e = e0; e < E; e++)
            g_rank[e] = atomicAdd(&g_deg[__ldg(row + e)], 1);
    }

    if (i >= NH4) return;
    int rw  = i >> 3;
    int sub = i & 7;

    const float4* base;
    const float4* sem;
    int r;
    float a;
    if (rw < U_CNT) { a = sigm(__ldg(ulw)); base = ue; sem = se; r = rw; }
    else            { a = sigm(__ldg(ilw)); base = ie; sem = he; r = rw - U_CNT; }

    float4 b0 = __ldcs(&base[r * ROW_F4 + sub * 2]);
    float4 b1 = __ldcs(&base[r * ROW_F4 + sub * 2 + 1]);
    float4 s0 = __ldcs(&sem [r * ROW_F4 + sub * 2]);
    float4 s1 = __ldcs(&sem [r * ROW_F4 + sub * 2 + 1]);

    float xs[8] = { s0.x, s0.y, s0.z, s0.w, s1.x, s1.y, s1.z, s1.w };
    float xb[8] = { b0.x, b0.y, b0.z, b0.w, b1.x, b1.y, b1.z, b1.w };
    float x[8];
    #pragma unroll
    for (int k = 0; k < 8; k++) x[k] = a * xb[k] + (1.0f - a) * xs[k];

    g_sem[i]   = pack8(xs);
    g_Lh[0][i] = pack8(x);
}

// ---------------------------------------------------------------------------
// Scan 1: warp-shuffle block scan of degrees + degree-bin histogram.
// Last finished block scans the 196 block sums AND the 256 degree bins.
// ---------------------------------------------------------------------------
__global__ void k_scan1()
{
    __shared__ int sw[32];
    __shared__ int sbuf[256];
    __shared__ int isLast;
    int i    = blockIdx.x * SCAN_BLK + threadIdx.x;
    int lane = threadIdx.x & 31;
    int wid  = threadIdx.x >> 5;

    int v = (i < N_CNT) ? g_deg[i] : 0;

    // warp inclusive scan
    int x = v;
    #pragma unroll
    for (int off = 1; off < 32; off <<= 1) {
        int y = __shfl_up_sync(0xffffffffu, x, off);
        if (lane >= off) x += y;
    }
    if (lane == 31) sw[wid] = x;
    __syncthreads();

    // scan the 32 warp sums in warp 0
    if (wid == 0) {
        int wv = sw[lane];
        int wx = wv;
        #pragma unroll
        for (int off = 1; off < 32; off <<= 1) {
            int y = __shfl_up_sync(0xffffffffu, wx, off);
            if (lane >= off) wx += y;
        }
        sw[lane] = wx - wv;   // exclusive warp offsets
    }
    __syncthreads();

    int incl = x + sw[wid];
    if (i < N_CNT) g_ptr[i] = incl - v;             // exclusive, block-local
    if (threadIdx.x == SCAN_BLK - 1) g_bsum[blockIdx.x] = incl;

    // degree-bin histogram (g_dbin == 0 on entry, invariant)
    if (i < N_CNT) {
        int d = v < DBINS ? v : DBINS - 1;
        atomicAdd(&g_dbin[d], 1);
    }

    __threadfence();
    if (threadIdx.x == 0)
        isLast = (atomicAdd(&g_tick, 1) == (int)gridDim.x - 1);
    __syncthreads();
    if (!isLast) return;

    int t = threadIdx.x;

    // exclusive scan of block sums (196 values, 256-wide Hillis-Steele)
    int v2 = (t < SCAN_NB) ? g_bsum[t] : 0;
    if (t < 256) sbuf[t] = v2;
    __syncthreads();
    for (int off = 1; off < 256; off <<= 1) {
        int u = (t < 256 && t >= off) ? sbuf[t - off] : 0;
        __syncthreads();
        if (t < 256) sbuf[t] += u;
        __syncthreads();
    }
    if (t < SCAN_NB) g_bsum[t] = sbuf[t] - v2;
    if (t == SCAN_NB - 1) g_ptr[N_CNT] = sbuf[t];
    __syncthreads();

    // exclusive scan of degree bins (256 values)
    int v3 = (t < DBINS) ? g_dbin[t] : 0;
    if (t < 256) sbuf[t] = v3;
    __syncthreads();
    for (int off = 1; off < 256; off <<= 1) {
        int u = (t < 256 && t >= off) ? sbuf[t - off] : 0;
        __syncthreads();
        if (t < 256) sbuf[t] += u;
        __syncthreads();
    }
    if (t < DBINS) g_dbin[t] = sbuf[t] - v3;

    if (t == 0) g_tick = 0;   // restore invariant
}

// ---------------------------------------------------------------------------
// Scan 3 + row ordering: finalize ptr; counting-sort rows into DESCENDING
// degree order (LPT). Re-zero g_deg (invariant).
// ---------------------------------------------------------------------------
__global__ void k_scan3()
{
    int i = blockIdx.x * blockDim.x + threadIdx.x;
    if (i >= N_CNT) return;
    int p = g_ptr[i] + g_bsum[i / SCAN_BLK];
    g_ptr[i] = p;
    int d = g_deg[i];
    d = d < DBINS ? d : DBINS - 1;
    int pos = atomicAdd(&g_dbin[d], 1);
    g_order[N_CNT - 1 - pos] = i;
    g_deg[i] = 0;             // restore invariant
}

// ---------------------------------------------------------------------------
// Atomic-free scatter: slot = ptr[row] + rank[e]. All reads coalesced except
// the small L2-resident ptr table. Also re-zeroes g_dbin (invariant).
// ---------------------------------------------------------------------------
__global__ void k_scatter(const int* __restrict__ row, const int* __restrict__ col,
                          const float* __restrict__ val, int E)
{
    int i = blockIdx.x * blockDim.x + threadIdx.x;
    if (blockIdx.x == 0 && threadIdx.x < DBINS) g_dbin[threadIdx.x] = 0;

    int e0 = i * 4;
    if (e0 >= E) return;
    if (e0 + 3 < E) {
        int4   r4 = __ldg((const int4*)(row + e0));
        int4   c4 = __ldg((const int4*)(col + e0));
        float4 v4 = __ldg((const float4*)(val + e0));
        int4   k4 = *(const int4*)(g_rank + e0);
        int r[4] = { r4.x, r4.y, r4.z, r4.w };
        int c[4] = { c4.x, c4.y, c4.z, c4.w };
        int kk[4] = { k4.x, k4.y, k4.z, k4.w };
        float v[4] = { v4.x, v4.y, v4.z, v4.w };
        int p[4];
        #pragma unroll
        for (int k = 0; k < 4; k++) p[k] = __ldg(&g_ptr[r[k]]) + kk[k];
        #pragma unroll
        for (int k = 0; k < 4; k++) {
            int q = __float2int_rn(v[k] * VAL_ENC_SCALE);
            q = q < 16383 ? q : 16383;
            g_csr[p[k]] = (unsigned)c[k] | ((unsigned)q << 18);
        }
    } else {
        for (int e = e0; e < E; e++) {
            int p = __ldg(&g_ptr[__ldg(row + e)]) + g_rank[e];
            int q = __float2int_rn(__ldg(val + e) * VAL_ENC_SCALE);
            q = q < 16383 ? q : 16383;
            g_csr[p] = (unsigned)__ldg(col + e) | ((unsigned)q << 18);
        }
    }
}

// ---------------------------------------------------------------------------
// Fused gather-SpMM (fp16 src, fp32 accum) + layer mix; fp16 dst (plain
// store — dst is the next layer's gather source, keep it in L2).
// ---------------------------------------------------------------------------
__global__ void k_spmm_fused(const float* __restrict__ ulw, const float* __restrict__ ilw,
                             int layer)
{
    int t = blockIdx.x * blockDim.x + threadIdx.x;
    int g = t >> 3;
    if (g >= N_CNT) return;
    int sub = t & 7;
    int rw = __ldg(&g_order[g]);

    const uint4* __restrict__ src = g_Lh[layer - 1];
    uint4*       __restrict__ dst = g_Lh[layer];

    int start = __ldg(&g_ptr[rw]);
    int end   = __ldg(&g_ptr[rw + 1]);

    float acc[8];
    #pragma unroll
    for (int k = 0; k < 8; k++) acc[k] = 0.0f;

    int j = start;
    for (; j + 4 <= end; j += 4) {
        unsigned e0 = __ldg(&g_csr[j + 0]);
        unsigned e1 = __ldg(&g_csr[j + 1]);
        unsigned e2 = __ldg(&g_csr[j + 2]);
        unsigned e3 = __ldg(&g_csr[j + 3]);
        uint4 q0 = __ldg(&src[(e0 & 0x3FFFFu) * ROW_H4 + sub]);
        uint4 q1 = __ldg(&src[(e1 & 0x3FFFFu) * ROW_H4 + sub]);
        uint4 q2 = __ldg(&src[(e2 & 0x3FFFFu) * ROW_H4 + sub]);
        uint4 q3 = __ldg(&src[(e3 & 0x3FFFFu) * ROW_H4 + sub]);
        acc8(acc, q0, (float)(e0 >> 18) * VAL_DEC_SCALE);
        acc8(acc, q1, (float)(e1 >> 18) * VAL_DEC_SCALE);
        acc8(acc, q2, (float)(e2 >> 18) * VAL_DEC_SCALE);
        acc8(acc, q3, (float)(e3 >> 18) * VAL_DEC_SCALE);
    }
    for (; j < end; j++) {
        unsigned e0 = __ldg(&g_csr[j]);
        uint4 q0 = __ldg(&src[(e0 & 0x3FFFFu) * ROW_H4 + sub]);
        acc8(acc, q0, (float)(e0 >> 18) * VAL_DEC_SCALE);
    }

    float a = (rw < U_CNT) ? sigm(__ldg(ulw + layer)) : sigm(__ldg(ilw + layer));

    float o[8];
    unpack8(__ldg(&g_sem[rw * ROW_H4 + sub]), o);

    float x[8];
    #pragma unroll
    for (int k = 0; k < 8; k++) x[k] = a * acc[k] + (1.0f - a) * o[k];

    dst[rw * ROW_H4 + sub] = pack8(x);
}

// ---------------------------------------------------------------------------
// Final dot: 8 lanes per (user, item) pair; sum 4 layer rows in fp32.
// ---------------------------------------------------------------------------
__global__ void k_dot(const int* __restrict__ users, const int* __restrict__ items,
                      float* __restrict__ out, int B)
{
    int t = blockIdx.x * blockDim.x + threadIdx.x;
    int b = t >> 3;
    if (b >= B) return;
    int sub = t & 7;

    int u  = __ldg(users + b);
    int it = __ldg(items + b);

    float su[8], si[8];
    #pragma unroll
    for (int k = 0; k < 8; k++) { su[k] = 0.0f; si[k] = 0.0f; }

    #pragma unroll
    for (int l = 0; l <= L_LAYERS; l++) {
        float xu[8], xi[8];
        unpack8(__ldg(&g_Lh[l][u * ROW_H4 + sub]), xu);
        unpack8(__ldg(&g_Lh[l][(U_CNT + it) * ROW_H4 + sub]), xi);
        #pragma unroll
        for (int k = 0; k < 8; k++) { su[k] += xu[k]; si[k] += xi[k]; }
    }

    float s = 0.0f;
    #pragma unroll
    for (int k = 0; k < 8; k++) s = fmaf(su[k], si[k], s);

    s += __shfl_down_sync(0xffffffffu, s, 4, 8);
    s += __shfl_down_sync(0xffffffffu, s, 2, 8);
    s += __shfl_down_sync(0xffffffffu, s, 1, 8);

    if (sub == 0) out[b] = s * (1.0f / ((L_LAYERS + 1) * (L_LAYERS + 1)));
}

// ---------------------------------------------------------------------------
// Launch sequence: init+hist+rank | scan1(+finals) | scan3(+order) | scatter |
// 3x fused SpMM | dot.   (8 launches)
// ---------------------------------------------------------------------------
extern "C" void kernel_launch(void* const* d_in, const int* in_sizes, int n_in,
                              void* d_out, int out_size)
{
    const float4* user_emb    = (const float4*)d_in[0];
    const float4* item_emb    = (const float4*)d_in[1];
    const float4* symptom_emb = (const float4*)d_in[2];
    const float4* herb_emb    = (const float4*)d_in[3];
    const float*  user_lw     = (const float*)d_in[4];
    const float*  item_lw     = (const float*)d_in[5];
    const float*  edge_val    = (const float*)d_in[6];
    const int*    edge_row    = (const int*)d_in[7];
    const int*    edge_col    = (const int*)d_in[8];
    const int*    users       = (const int*)d_in[9];
    const int*    items       = (const int*)d_in[10];

    int E = in_sizes[6];
    int B = in_sizes[9];

    const int TB = 256;

    int e4 = (E + 3) / 4;
    int init_blocks = ((NH4 > e4 ? NH4 : e4) + TB - 1) / TB;
    k_init_hist<<<init_blocks, TB>>>(user_emb, item_emb, symptom_emb, herb_emb,
                                     user_lw, item_lw, edge_row, E);
    k_scan1<<<SCAN_NB, SCAN_BLK>>>();
    k_scan3<<<(N_CNT + TB - 1) / TB, TB>>>();
    k_scatter<<<(e4 + TB - 1) / TB, TB>>>(edge_row, edge_col, edge_val, E);

    int spmm_blocks = (N_CNT * 8 + TB - 1) / TB;
    for (int layer = 1; layer <= L_LAYERS; layer++) {
        k_spmm_fused<<<spmm_blocks, TB>>>(user_lw, item_lw, layer);
    }

    k_dot<<<(B * 8 + TB - 1) / TB, TB>>>(users, items, (float*)d_out, B);
}

// round 7
// speedup vs baseline: 1.0555x; 1.0555x over previous
#include <cuda_runtime.h>
#include <cuda_fp16.h>
#include <cuda_bf16.h>

// Problem constants (fixed by the reference).
#define U_CNT 100000
#define I_CNT 100000
#define N_CNT 200000           // U + I
#define L_LAYERS 3
#define ROW_F4 16              // D/4 float4 per node row (fp32 inputs)
#define ROW_H4 8               // 8 uint4 per node row (64 halves, 128B)
#define NH4   (N_CNT * ROW_H4) // 1.6M uint4 = 25.6 MB per layer buffer
#define E_MAX 6400000
#define SCAN_BLK 1024
#define SCAN_NB ((N_CNT + SCAN_BLK - 1) / SCAN_BLK)   // 196
#define DBINS 256

// val quantization: val in [0, 1/32), 14-bit fixed point in bits [18,32).
#define VAL_ENC_SCALE (32.0f * 16383.0f)
#define VAL_DEC_SCALE (1.0f / (32.0f * 16383.0f))

// Scratch (__device__ globals only — allocation-free rule).
// Steady-state invariants maintained across calls (zero-init by loader first):
//   g_deg  == 0 on entry (re-zeroed in k_scan3)
//   g_dbin == 0 on entry (re-zeroed in k_scatter)
//   g_tick == 0 on entry (re-zeroed by scan1's last block)
__device__ uint4    g_Lh[L_LAYERS + 1][NH4];   // 4 x 25.6 MB fp16 layer buffers
__device__ uint4    g_sem[NH4];                // fp16 semantic (symptom|herb) table
__device__ unsigned g_csr [E_MAX];             // packed (col | q<<18), grouped by row
__device__ int      g_deg [N_CNT];
__device__ int      g_ptr [N_CNT + 1];
__device__ int      g_cursor[N_CNT];
__device__ int      g_bsum[SCAN_NB];
__device__ int      g_dbin[DBINS];             // degree histogram -> cursor
__device__ int      g_order[N_CNT];            // rows in DESCENDING degree order
__device__ int      g_tick;

__device__ __forceinline__ float sigm(float x) { return 1.0f / (1.0f + __expf(-x)); }

__device__ __forceinline__ uint4 pack8(const float* x)
{
    uint4 r;
    half2 h0 = __floats2half2_rn(x[0], x[1]);
    half2 h1 = __floats2half2_rn(x[2], x[3]);
    half2 h2 = __floats2half2_rn(x[4], x[5]);
    half2 h3 = __floats2half2_rn(x[6], x[7]);
    r.x = *(unsigned*)&h0; r.y = *(unsigned*)&h1;
    r.z = *(unsigned*)&h2; r.w = *(unsigned*)&h3;
    return r;
}

__device__ __forceinline__ void unpack8(uint4 q, float* x)
{
    half2* hp = (half2*)&q;
    float2 f0 = __half22float2(hp[0]);
    float2 f1 = __half22float2(hp[1]);
    float2 f2 = __half22float2(hp[2]);
    float2 f3 = __half22float2(hp[3]);
    x[0] = f0.x; x[1] = f0.y; x[2] = f1.x; x[3] = f1.y;
    x[4] = f2.x; x[5] = f2.y; x[6] = f3.x; x[7] = f3.y;
}

__device__ __forceinline__ void acc8(float* acc, uint4 q, float v)
{
    float x[8];
    unpack8(q, x);
    #pragma unroll
    for (int k = 0; k < 8; k++) acc[k] = fmaf(v, x[k], acc[k]);
}

// ---------------------------------------------------------------------------
// Fused: layer-0 mix -> g_Lh[0] (fp16), semantic table -> g_sem (fp16),
// and edge-row degree histogram (fire-and-forget REDG atomics — no return).
// Requires g_deg == 0 on entry (invariant).
// ---------------------------------------------------------------------------
__global__ void k_init_hist(const float4* __restrict__ ue, const float4* __restrict__ ie,
                            const float4* __restrict__ se, const float4* __restrict__ he,
                            const float*  __restrict__ ulw, const float* __restrict__ ilw,
                            const int*    __restrict__ row, int E)
{
    int i = blockIdx.x * blockDim.x + threadIdx.x;

    // degree histogram: 4 edges per thread (return value unused -> REDG)
    int e0 = i * 4;
    if (e0 + 3 < E) {
        int4 r4 = __ldg((const int4*)(row + e0));
        atomicAdd(&g_deg[r4.x], 1);
        atomicAdd(&g_deg[r4.y], 1);
        atomicAdd(&g_deg[r4.z], 1);
        atomicAdd(&g_deg[r4.w], 1);
    } else if (e0 < E) {
        for (int e = e0; e < E; e++) atomicAdd(&g_deg[__ldg(row + e)], 1);
    }

    if (i >= NH4) return;
    int rw  = i >> 3;
    int sub = i & 7;

    const float4* base;
    const float4* sem;
    int r;
    float a;
    if (rw < U_CNT) { a = sigm(__ldg(ulw)); base = ue; sem = se; r = rw; }
    else            { a = sigm(__ldg(ilw)); base = ie; sem = he; r = rw - U_CNT; }

    float4 b0 = __ldcs(&base[r * ROW_F4 + sub * 2]);
    float4 b1 = __ldcs(&base[r * ROW_F4 + sub * 2 + 1]);
    float4 s0 = __ldcs(&sem [r * ROW_F4 + sub * 2]);
    float4 s1 = __ldcs(&sem [r * ROW_F4 + sub * 2 + 1]);

    float xs[8] = { s0.x, s0.y, s0.z, s0.w, s1.x, s1.y, s1.z, s1.w };
    float xb[8] = { b0.x, b0.y, b0.z, b0.w, b1.x, b1.y, b1.z, b1.w };
    float x[8];
    #pragma unroll
    for (int k = 0; k < 8; k++) x[k] = a * xb[k] + (1.0f - a) * xs[k];

    g_sem[i]   = pack8(xs);
    g_Lh[0][i] = pack8(x);
}

// ---------------------------------------------------------------------------
// Scan 1: warp-shuffle block scan of degrees + degree-bin histogram.
// Last finished block scans the 196 block sums AND the 256 degree bins.
// ---------------------------------------------------------------------------
__global__ void k_scan1()
{
    __shared__ int sw[32];
    __shared__ int sbuf[256];
    __shared__ int isLast;
    int i    = blockIdx.x * SCAN_BLK + threadIdx.x;
    int lane = threadIdx.x & 31;
    int wid  = threadIdx.x >> 5;

    int v = (i < N_CNT) ? g_deg[i] : 0;

    // warp inclusive scan
    int x = v;
    #pragma unroll
    for (int off = 1; off < 32; off <<= 1) {
        int y = __shfl_up_sync(0xffffffffu, x, off);
        if (lane >= off) x += y;
    }
    if (lane == 31) sw[wid] = x;
    __syncthreads();

    // scan the 32 warp sums in warp 0
    if (wid == 0) {
        int wv = sw[lane];
        int wx = wv;
        #pragma unroll
        for (int off = 1; off < 32; off <<= 1) {
            int y = __shfl_up_sync(0xffffffffu, wx, off);
            if (lane >= off) wx += y;
        }
        sw[lane] = wx - wv;   // exclusive warp offsets
    }
    __syncthreads();

    int incl = x + sw[wid];
    if (i < N_CNT) g_ptr[i] = incl - v;             // exclusive, block-local
    if (threadIdx.x == SCAN_BLK - 1) g_bsum[blockIdx.x] = incl;

    // degree-bin histogram (g_dbin == 0 on entry, invariant)
    if (i < N_CNT) {
        int d = v < DBINS ? v : DBINS - 1;
        atomicAdd(&g_dbin[d], 1);
    }

    __threadfence();
    if (threadIdx.x == 0)
        isLast = (atomicAdd(&g_tick, 1) == (int)gridDim.x - 1);
    __syncthreads();
    if (!isLast) return;

    int t = threadIdx.x;

    // exclusive scan of block sums (196 values, 256-wide Hillis-Steele)
    int v2 = (t < SCAN_NB) ? g_bsum[t] : 0;
    if (t < 256) sbuf[t] = v2;
    __syncthreads();
    for (int off = 1; off < 256; off <<= 1) {
        int u = (t < 256 && t >= off) ? sbuf[t - off] : 0;
        __syncthreads();
        if (t < 256) sbuf[t] += u;
        __syncthreads();
    }
    if (t < SCAN_NB) g_bsum[t] = sbuf[t] - v2;
    if (t == SCAN_NB - 1) g_ptr[N_CNT] = sbuf[t];
    __syncthreads();

    // exclusive scan of degree bins (256 values)
    int v3 = (t < DBINS) ? g_dbin[t] : 0;
    if (t < 256) sbuf[t] = v3;
    __syncthreads();
    for (int off = 1; off < 256; off <<= 1) {
        int u = (t < 256 && t >= off) ? sbuf[t - off] : 0;
        __syncthreads();
        if (t < 256) sbuf[t] += u;
        __syncthreads();
    }
    if (t < DBINS) g_dbin[t] = sbuf[t] - v3;

    if (t == 0) g_tick = 0;   // restore invariant
}

// ---------------------------------------------------------------------------
// Scan 3 + row ordering: finalize ptr/cursor; counting-sort rows into
// DESCENDING degree order (LPT). Re-zero g_deg (invariant).
// ---------------------------------------------------------------------------
__global__ void k_scan3()
{
    int i = blockIdx.x * blockDim.x + threadIdx.x;
    if (i >= N_CNT) return;
    int p = g_ptr[i] + g_bsum[i / SCAN_BLK];
    g_ptr[i]    = p;
    g_cursor[i] = p;
    int d = g_deg[i];
    d = d < DBINS ? d : DBINS - 1;
    int pos = atomicAdd(&g_dbin[d], 1);
    g_order[N_CNT - 1 - pos] = i;
    g_deg[i] = 0;             // restore invariant
}

// ---------------------------------------------------------------------------
// Scatter edges into packed CSR: 8 edges/thread (independent atomic->store
// chains for MLP). Also re-zeroes g_dbin (invariant).
// ---------------------------------------------------------------------------
__global__ void k_scatter(const int* __restrict__ row, const int* __restrict__ col,
                          const float* __restrict__ val, int E)
{
    int i = blockIdx.x * blockDim.x + threadIdx.x;
    if (blockIdx.x == 0 && threadIdx.x < DBINS) g_dbin[threadIdx.x] = 0;

    int e0 = i * 8;
    if (e0 >= E) return;
    if (e0 + 7 < E) {
        int4   ra = __ldg((const int4*)(row + e0));
        int4   rb = __ldg((const int4*)(row + e0 + 4));
        int4   ca = __ldg((const int4*)(col + e0));
        int4   cb = __ldg((const int4*)(col + e0 + 4));
        float4 va = __ldg((const float4*)(val + e0));
        float4 vb = __ldg((const float4*)(val + e0 + 4));
        int r[8]   = { ra.x, ra.y, ra.z, ra.w, rb.x, rb.y, rb.z, rb.w };
        int c[8]   = { ca.x, ca.y, ca.z, ca.w, cb.x, cb.y, cb.z, cb.w };
        float v[8] = { va.x, va.y, va.z, va.w, vb.x, vb.y, vb.z, vb.w };
        int p[8];
        #pragma unroll
        for (int k = 0; k < 8; k++) p[k] = atomicAdd(&g_cursor[r[k]], 1);
        #pragma unroll
        for (int k = 0; k < 8; k++) {
            int q = __float2int_rn(v[k] * VAL_ENC_SCALE);
            q = q < 16383 ? q : 16383;
            __stcs(&g_csr[p[k]], (unsigned)c[k] | ((unsigned)q << 18));
        }
    } else {
        for (int e = e0; e < E; e++) {
            int p = atomicAdd(&g_cursor[__ldg(row + e)], 1);
            int q = __float2int_rn(__ldg(val + e) * VAL_ENC_SCALE);
            q = q < 16383 ? q : 16383;
            __stcs(&g_csr[p], (unsigned)__ldg(col + e) | ((unsigned)q << 18));
        }
    }
}

// ---------------------------------------------------------------------------
// Fused gather-SpMM (fp16 src, fp32 accum) + layer mix; fp16 dst.
// 8 lanes per row; rows in descending-degree order; edge loop unrolled x8.
// ---------------------------------------------------------------------------
__global__ void k_spmm_fused(const float* __restrict__ ulw, const float* __restrict__ ilw,
                             int layer)
{
    int t = blockIdx.x * blockDim.x + threadIdx.x;
    int g = t >> 3;
    if (g >= N_CNT) return;
    int sub = t & 7;
    int rw = __ldg(&g_order[g]);

    const uint4* __restrict__ src = g_Lh[layer - 1];
    uint4*       __restrict__ dst = g_Lh[layer];

    int start = __ldg(&g_ptr[rw]);
    int end   = __ldg(&g_ptr[rw + 1]);

    float acc[8];
    #pragma unroll
    for (int k = 0; k < 8; k++) acc[k] = 0.0f;

    int j = start;
    for (; j + 8 <= end; j += 8) {
        unsigned e[8];
        #pragma unroll
        for (int k = 0; k < 8; k++) e[k] = __ldg(&g_csr[j + k]);
        uint4 q[8];
        #pragma unroll
        for (int k = 0; k < 8; k++) q[k] = __ldg(&src[(e[k] & 0x3FFFFu) * ROW_H4 + sub]);
        #pragma unroll
        for (int k = 0; k < 8; k++) acc8(acc, q[k], (float)(e[k] >> 18) * VAL_DEC_SCALE);
    }
    for (; j + 4 <= end; j += 4) {
        unsigned e0 = __ldg(&g_csr[j + 0]);
        unsigned e1 = __ldg(&g_csr[j + 1]);
        unsigned e2 = __ldg(&g_csr[j + 2]);
        unsigned e3 = __ldg(&g_csr[j + 3]);
        uint4 q0 = __ldg(&src[(e0 & 0x3FFFFu) * ROW_H4 + sub]);
        uint4 q1 = __ldg(&src[(e1 & 0x3FFFFu) * ROW_H4 + sub]);
        uint4 q2 = __ldg(&src[(e2 & 0x3FFFFu) * ROW_H4 + sub]);
        uint4 q3 = __ldg(&src[(e3 & 0x3FFFFu) * ROW_H4 + sub]);
        acc8(acc, q0, (float)(e0 >> 18) * VAL_DEC_SCALE);
        acc8(acc, q1, (float)(e1 >> 18) * VAL_DEC_SCALE);
        acc8(acc, q2, (float)(e2 >> 18) * VAL_DEC_SCALE);
        acc8(acc, q3, (float)(e3 >> 18) * VAL_DEC_SCALE);
    }
    for (; j < end; j++) {
        unsigned e0 = __ldg(&g_csr[j]);
        uint4 q0 = __ldg(&src[(e0 & 0x3FFFFu) * ROW_H4 + sub]);
        acc8(acc, q0, (float)(e0 >> 18) * VAL_DEC_SCALE);
    }

    float a = (rw < U_CNT) ? sigm(__ldg(ulw + layer)) : sigm(__ldg(ilw + layer));

    float o[8];
    unpack8(__ldg(&g_sem[rw * ROW_H4 + sub]), o);

    float x[8];
    #pragma unroll
    for (int k = 0; k < 8; k++) x[k] = a * acc[k] + (1.0f - a) * o[k];

    __stcs(&dst[rw * ROW_H4 + sub], pack8(x));
}

// ---------------------------------------------------------------------------
// Final dot: 8 lanes per (user, item) pair; sum 4 layer rows in fp32.
// ---------------------------------------------------------------------------
__global__ void k_dot(const int* __restrict__ users, const int* __restrict__ items,
                      float* __restrict__ out, int B)
{
    int t = blockIdx.x * blockDim.x + threadIdx.x;
    int b = t >> 3;
    if (b >= B) return;
    int sub = t & 7;

    int u  = __ldg(users + b);
    int it = __ldg(items + b);

    float su[8], si[8];
    #pragma unroll
    for (int k = 0; k < 8; k++) { su[k] = 0.0f; si[k] = 0.0f; }

    #pragma unroll
    for (int l = 0; l <= L_LAYERS; l++) {
        float xu[8], xi[8];
        unpack8(__ldg(&g_Lh[l][u * ROW_H4 + sub]), xu);
        unpack8(__ldg(&g_Lh[l][(U_CNT + it) * ROW_H4 + sub]), xi);
        #pragma unroll
        for (int k = 0; k < 8; k++) { su[k] += xu[k]; si[k] += xi[k]; }
    }

    float s = 0.0f;
    #pragma unroll
    for (int k = 0; k < 8; k++) s = fmaf(su[k], si[k], s);

    s += __shfl_down_sync(0xffffffffu, s, 4, 8);
    s += __shfl_down_sync(0xffffffffu, s, 2, 8);
    s += __shfl_down_sync(0xffffffffu, s, 1, 8);

    if (sub == 0) out[b] = s * (1.0f / ((L_LAYERS + 1) * (L_LAYERS + 1)));
}

// ---------------------------------------------------------------------------
// Launch sequence: init+hist | scan1(+finals) | scan3(+order) | scatter |
// 3x fused SpMM | dot.   (8 launches)
// ---------------------------------------------------------------------------
extern "C" void kernel_launch(void* const* d_in, const int* in_sizes, int n_in,
                              void* d_out, int out_size)
{
    const float4* user_emb    = (const float4*)d_in[0];
    const float4* item_emb    = (const float4*)d_in[1];
    const float4* symptom_emb = (const float4*)d_in[2];
    const float4* herb_emb    = (const float4*)d_in[3];
    const float*  user_lw     = (const float*)d_in[4];
    const float*  item_lw     = (const float*)d_in[5];
    const float*  edge_val    = (const float*)d_in[6];
    const int*    edge_row    = (const int*)d_in[7];
    const int*    edge_col    = (const int*)d_in[8];
    const int*    users       = (const int*)d_in[9];
    const int*    items       = (const int*)d_in[10];

    int E = in_sizes[6];
    int B = in_sizes[9];

    const int TB = 256;

    int e4 = (E + 3) / 4;
    int init_blocks = ((NH4 > e4 ? NH4 : e4) + TB - 1) / TB;
    k_init_hist<<<init_blocks, TB>>>(user_emb, item_emb, symptom_emb, herb_emb,
                                     user_lw, item_lw, edge_row, E);
    k_scan1<<<SCAN_NB, SCAN_BLK>>>();
    k_scan3<<<(N_CNT + TB - 1) / TB, TB>>>();

    int e8 = (E + 7) / 8;
    k_scatter<<<(e8 + TB - 1) / TB, TB>>>(edge_row, edge_col, edge_val, E);

    int spmm_blocks = (N_CNT * 8 + TB - 1) / TB;
    for (int layer = 1; layer <= L_LAYERS; layer++) {
        k_spmm_fused<<<spmm_blocks, TB>>>(user_lw, item_lw, layer);
    }

    k_dot<<<(B * 8 + TB - 1) / TB, TB>>>(users, items, (float*)d_out, B);
}

// round 8
// speedup vs baseline: 1.1384x; 1.0786x over previous
#include <cuda_runtime.h>
#include <cuda_fp16.h>
#include <cuda_bf16.h>

// Problem constants (fixed by the reference).
#define U_CNT 100000
#define I_CNT 100000
#define N_CNT 200000           // U + I
#define L_LAYERS 3
#define ROW_F4 16              // D/4 float4 per node row (fp32 inputs)
#define ROW_H4 8               // 8 uint4 per node row (64 halves, 128B)
#define NH4   (N_CNT * ROW_H4) // 1.6M uint4 = 25.6 MB per layer buffer
#define E_MAX 6400000
#define SCAN_BLK 1024
#define SCAN_NB ((N_CNT + SCAN_BLK - 1) / SCAN_BLK)   // 196
#define DBINS 256

// val quantization: val in [0, 1/32), 14-bit fixed point in bits [18,32).
#define VAL_ENC_SCALE (32.0f * 16383.0f)
#define VAL_DEC_SCALE (1.0f / (32.0f * 16383.0f))

// Scratch (__device__ globals only — allocation-free rule).
// Steady-state invariants maintained across calls (zero-init by loader first):
//   g_deg  == 0 on entry (re-zeroed in k_scan3)
//   g_dbin == 0 on entry (re-zeroed in k_scatter_init)
//   g_tick == 0 on entry (re-zeroed by scan1's last block)
__device__ uint4    g_Lh[L_LAYERS + 1][NH4];   // 4 x 25.6 MB fp16 layer buffers
__device__ uint4    g_sem[NH4];                // fp16 semantic (symptom|herb) table
__device__ unsigned g_csr [E_MAX];             // packed (col | q<<18), grouped by row
__device__ int      g_deg [N_CNT];
__device__ int      g_ptr [N_CNT + 1];
__device__ int      g_cursor[N_CNT];
__device__ int      g_bsum[SCAN_NB];
__device__ int      g_dbin[DBINS];             // degree histogram -> cursor
__device__ int      g_order[N_CNT];            // rows in DESCENDING degree order
__device__ int      g_tick;

__device__ __forceinline__ float sigm(float x) { return 1.0f / (1.0f + __expf(-x)); }

__device__ __forceinline__ uint4 pack8(const float* x)
{
    uint4 r;
    half2 h0 = __floats2half2_rn(x[0], x[1]);
    half2 h1 = __floats2half2_rn(x[2], x[3]);
    half2 h2 = __floats2half2_rn(x[4], x[5]);
    half2 h3 = __floats2half2_rn(x[6], x[7]);
    r.x = *(unsigned*)&h0; r.y = *(unsigned*)&h1;
    r.z = *(unsigned*)&h2; r.w = *(unsigned*)&h3;
    return r;
}

__device__ __forceinline__ void unpack8(uint4 q, float* x)
{
    half2* hp = (half2*)&q;
    float2 f0 = __half22float2(hp[0]);
    float2 f1 = __half22float2(hp[1]);
    float2 f2 = __half22float2(hp[2]);
    float2 f3 = __half22float2(hp[3]);
    x[0] = f0.x; x[1] = f0.y; x[2] = f1.x; x[3] = f1.y;
    x[4] = f2.x; x[5] = f2.y; x[6] = f3.x; x[7] = f3.y;
}

__device__ __forceinline__ void acc8(float* acc, uint4 q, float v)
{
    float x[8];
    unpack8(q, x);
    #pragma unroll
    for (int k = 0; k < 8; k++) acc[k] = fmaf(v, x[k], acc[k]);
}

// ---------------------------------------------------------------------------
// Degree histogram only: fire-and-forget REDG atomics, 4 edges/thread.
// Requires g_deg == 0 on entry (invariant).
// ---------------------------------------------------------------------------
__global__ void k_hist(const int* __restrict__ row, int E)
{
    int i = blockIdx.x * blockDim.x + threadIdx.x;
    int e0 = i * 4;
    if (e0 + 3 < E) {
        int4 r4 = __ldg((const int4*)(row + e0));
        atomicAdd(&g_deg[r4.x], 1);
        atomicAdd(&g_deg[r4.y], 1);
        atomicAdd(&g_deg[r4.z], 1);
        atomicAdd(&g_deg[r4.w], 1);
    } else if (e0 < E) {
        for (int e = e0; e < E; e++) atomicAdd(&g_deg[__ldg(row + e)], 1);
    }
}

// ---------------------------------------------------------------------------
// Scan 1: warp-shuffle block scan of degrees + degree-bin histogram.
// Last finished block scans the 196 block sums AND the 256 degree bins.
// ---------------------------------------------------------------------------
__global__ void k_scan1()
{
    __shared__ int sw[32];
    __shared__ int sbuf[256];
    __shared__ int isLast;
    int i    = blockIdx.x * SCAN_BLK + threadIdx.x;
    int lane = threadIdx.x & 31;
    int wid  = threadIdx.x >> 5;

    int v = (i < N_CNT) ? g_deg[i] : 0;

    // warp inclusive scan
    int x = v;
    #pragma unroll
    for (int off = 1; off < 32; off <<= 1) {
        int y = __shfl_up_sync(0xffffffffu, x, off);
        if (lane >= off) x += y;
    }
    if (lane == 31) sw[wid] = x;
    __syncthreads();

    // scan the 32 warp sums in warp 0
    if (wid == 0) {
        int wv = sw[lane];
        int wx = wv;
        #pragma unroll
        for (int off = 1; off < 32; off <<= 1) {
            int y = __shfl_up_sync(0xffffffffu, wx, off);
            if (lane >= off) wx += y;
        }
        sw[lane] = wx - wv;   // exclusive warp offsets
    }
    __syncthreads();

    int incl = x + sw[wid];
    if (i < N_CNT) g_ptr[i] = incl - v;             // exclusive, block-local
    if (threadIdx.x == SCAN_BLK - 1) g_bsum[blockIdx.x] = incl;

    // degree-bin histogram (g_dbin == 0 on entry, invariant)
    if (i < N_CNT) {
        int d = v < DBINS ? v : DBINS - 1;
        atomicAdd(&g_dbin[d], 1);
    }

    __threadfence();
    if (threadIdx.x == 0)
        isLast = (atomicAdd(&g_tick, 1) == (int)gridDim.x - 1);
    __syncthreads();
    if (!isLast) return;

    int t = threadIdx.x;

    // exclusive scan of block sums (196 values, 256-wide Hillis-Steele)
    int v2 = (t < SCAN_NB) ? g_bsum[t] : 0;
    if (t < 256) sbuf[t] = v2;
    __syncthreads();
    for (int off = 1; off < 256; off <<= 1) {
        int u = (t < 256 && t >= off) ? sbuf[t - off] : 0;
        __syncthreads();
        if (t < 256) sbuf[t] += u;
        __syncthreads();
    }
    if (t < SCAN_NB) g_bsum[t] = sbuf[t] - v2;
    if (t == SCAN_NB - 1) g_ptr[N_CNT] = sbuf[t];
    __syncthreads();

    // exclusive scan of degree bins (256 values)
    int v3 = (t < DBINS) ? g_dbin[t] : 0;
    if (t < 256) sbuf[t] = v3;
    __syncthreads();
    for (int off = 1; off < 256; off <<= 1) {
        int u = (t < 256 && t >= off) ? sbuf[t - off] : 0;
        __syncthreads();
        if (t < 256) sbuf[t] += u;
        __syncthreads();
    }
    if (t < DBINS) g_dbin[t] = sbuf[t] - v3;

    if (t == 0) g_tick = 0;   // restore invariant
}

// ---------------------------------------------------------------------------
// Scan 3 + row ordering: finalize ptr/cursor; counting-sort rows into
// DESCENDING degree order (LPT). Re-zero g_deg (invariant).
// ---------------------------------------------------------------------------
__global__ void k_scan3()
{
    int i = blockIdx.x * blockDim.x + threadIdx.x;
    if (i >= N_CNT) return;
    int p = g_ptr[i] + g_bsum[i / SCAN_BLK];
    g_ptr[i]    = p;
    g_cursor[i] = p;
    int d = g_deg[i];
    d = d < DBINS ? d : DBINS - 1;
    int pos = atomicAdd(&g_dbin[d], 1);
    g_order[N_CNT - 1 - pos] = i;
    g_deg[i] = 0;             // restore invariant
}

// ---------------------------------------------------------------------------
// FUSED scatter + init. Thread i:
//   (1) reserves CSR slots for edges 4i..4i+3 (4 independent ATOMG chains),
//   (2) computes init element i (layer-0 mix + fp16 sem table) — this DRAM
//       streaming work executes in the shadow of the atomic round-trips,
//   (3) stores the packed edges to their scattered CSR slots.
// E/4 == NH4 == 1.6M, so both workloads share the same thread space.
// Also re-zeroes g_dbin (invariant).
// ---------------------------------------------------------------------------
__global__ void k_scatter_init(const int*    __restrict__ row, const int* __restrict__ col,
                               const float*  __restrict__ val, int E,
                               const float4* __restrict__ ue, const float4* __restrict__ ie,
                               const float4* __restrict__ se, const float4* __restrict__ he,
                               const float*  __restrict__ ulw, const float* __restrict__ ilw)
{
    int i = blockIdx.x * blockDim.x + threadIdx.x;
    if (blockIdx.x == 0 && threadIdx.x < DBINS) g_dbin[threadIdx.x] = 0;

    // --- (1) slot reservation: issue all 4 atomics up front ---
    int e0 = i * 4;
    bool full = (e0 + 3 < E);
    int p[4], c[4];
    float v[4];
    if (full) {
        int4   r4 = __ldg((const int4*)(row + e0));
        int4   c4 = __ldg((const int4*)(col + e0));
        float4 v4 = __ldg((const float4*)(val + e0));
        c[0] = c4.x; c[1] = c4.y; c[2] = c4.z; c[3] = c4.w;
        v[0] = v4.x; v[1] = v4.y; v[2] = v4.z; v[3] = v4.w;
        p[0] = atomicAdd(&g_cursor[r4.x], 1);
        p[1] = atomicAdd(&g_cursor[r4.y], 1);
        p[2] = atomicAdd(&g_cursor[r4.z], 1);
        p[3] = atomicAdd(&g_cursor[r4.w], 1);
    }

    // --- (2) init element (independent streaming work hides atomic latency) ---
    if (i < NH4) {
        int rw  = i >> 3;
        int sub = i & 7;

        const float4* base;
        const float4* sem;
        int r;
        float a;
        if (rw < U_CNT) { a = sigm(__ldg(ulw)); base = ue; sem = se; r = rw; }
        else            { a = sigm(__ldg(ilw)); base = ie; sem = he; r = rw - U_CNT; }

        float4 b0 = __ldcs(&base[r * ROW_F4 + sub * 2]);
        float4 b1 = __ldcs(&base[r * ROW_F4 + sub * 2 + 1]);
        float4 s0 = __ldcs(&sem [r * ROW_F4 + sub * 2]);
        float4 s1 = __ldcs(&sem [r * ROW_F4 + sub * 2 + 1]);

        float xs[8] = { s0.x, s0.y, s0.z, s0.w, s1.x, s1.y, s1.z, s1.w };
        float xb[8] = { b0.x, b0.y, b0.z, b0.w, b1.x, b1.y, b1.z, b1.w };
        float x[8];
        #pragma unroll
        for (int k = 0; k < 8; k++) x[k] = a * xb[k] + (1.0f - a) * xs[k];

        g_sem[i]   = pack8(xs);
        g_Lh[0][i] = pack8(x);
    }

    // --- (3) scattered CSR stores ---
    if (full) {
        #pragma unroll
        for (int k = 0; k < 4; k++) {
            int q = __float2int_rn(v[k] * VAL_ENC_SCALE);
            q = q < 16383 ? q : 16383;
            __stcs(&g_csr[p[k]], (unsigned)c[k] | ((unsigned)q << 18));
        }
    } else if (e0 < E) {
        for (int e = e0; e < E; e++) {
            int pp = atomicAdd(&g_cursor[__ldg(row + e)], 1);
            int q = __float2int_rn(__ldg(val + e) * VAL_ENC_SCALE);
            q = q < 16383 ? q : 16383;
            __stcs(&g_csr[pp], (unsigned)__ldg(col + e) | ((unsigned)q << 18));
        }
    }
}

// ---------------------------------------------------------------------------
// Fused gather-SpMM (fp16 src, fp32 accum) + layer mix; fp16 dst.
// 8 lanes per row; rows in descending-degree order; edge loop unrolled x4
// (R5-proven configuration).
// ---------------------------------------------------------------------------
__global__ void k_spmm_fused(const float* __restrict__ ulw, const float* __restrict__ ilw,
                             int layer)
{
    int t = blockIdx.x * blockDim.x + threadIdx.x;
    int g = t >> 3;
    if (g >= N_CNT) return;
    int sub = t & 7;
    int rw = __ldg(&g_order[g]);

    const uint4* __restrict__ src = g_Lh[layer - 1];
    uint4*       __restrict__ dst = g_Lh[layer];

    int start = __ldg(&g_ptr[rw]);
    int end   = __ldg(&g_ptr[rw + 1]);

    float acc[8];
    #pragma unroll
    for (int k = 0; k < 8; k++) acc[k] = 0.0f;

    int j = start;
    for (; j + 4 <= end; j += 4) {
        unsigned e0 = __ldg(&g_csr[j + 0]);
        unsigned e1 = __ldg(&g_csr[j + 1]);
        unsigned e2 = __ldg(&g_csr[j + 2]);
        unsigned e3 = __ldg(&g_csr[j + 3]);
        uint4 q0 = __ldg(&src[(e0 & 0x3FFFFu) * ROW_H4 + sub]);
        uint4 q1 = __ldg(&src[(e1 & 0x3FFFFu) * ROW_H4 + sub]);
        uint4 q2 = __ldg(&src[(e2 & 0x3FFFFu) * ROW_H4 + sub]);
        uint4 q3 = __ldg(&src[(e3 & 0x3FFFFu) * ROW_H4 + sub]);
        acc8(acc, q0, (float)(e0 >> 18) * VAL_DEC_SCALE);
        acc8(acc, q1, (float)(e1 >> 18) * VAL_DEC_SCALE);
        acc8(acc, q2, (float)(e2 >> 18) * VAL_DEC_SCALE);
        acc8(acc, q3, (float)(e3 >> 18) * VAL_DEC_SCALE);
    }
    for (; j < end; j++) {
        unsigned e0 = __ldg(&g_csr[j]);
        uint4 q0 = __ldg(&src[(e0 & 0x3FFFFu) * ROW_H4 + sub]);
        acc8(acc, q0, (float)(e0 >> 18) * VAL_DEC_SCALE);
    }

    float a = (rw < U_CNT) ? sigm(__ldg(ulw + layer)) : sigm(__ldg(ilw + layer));

    float o[8];
    unpack8(__ldg(&g_sem[rw * ROW_H4 + sub]), o);

    float x[8];
    #pragma unroll
    for (int k = 0; k < 8; k++) x[k] = a * acc[k] + (1.0f - a) * o[k];

    __stcs(&dst[rw * ROW_H4 + sub], pack8(x));
}

// ---------------------------------------------------------------------------
// Final dot: 8 lanes per (user, item) pair; sum 4 layer rows in fp32.
// ---------------------------------------------------------------------------
__global__ void k_dot(const int* __restrict__ users, const int* __restrict__ items,
                      float* __restrict__ out, int B)
{
    int t = blockIdx.x * blockDim.x + threadIdx.x;
    int b = t >> 3;
    if (b >= B) return;
    int sub = t & 7;

    int u  = __ldg(users + b);
    int it = __ldg(items + b);

    float su[8], si[8];
    #pragma unroll
    for (int k = 0; k < 8; k++) { su[k] = 0.0f; si[k] = 0.0f; }

    #pragma unroll
    for (int l = 0; l <= L_LAYERS; l++) {
        float xu[8], xi[8];
        unpack8(__ldg(&g_Lh[l][u * ROW_H4 + sub]), xu);
        unpack8(__ldg(&g_Lh[l][(U_CNT + it) * ROW_H4 + sub]), xi);
        #pragma unroll
        for (int k = 0; k < 8; k++) { su[k] += xu[k]; si[k] += xi[k]; }
    }

    float s = 0.0f;
    #pragma unroll
    for (int k = 0; k < 8; k++) s = fmaf(su[k], si[k], s);

    s += __shfl_down_sync(0xffffffffu, s, 4, 8);
    s += __shfl_down_sync(0xffffffffu, s, 2, 8);
    s += __shfl_down_sync(0xffffffffu, s, 1, 8);

    if (sub == 0) out[b] = s * (1.0f / ((L_LAYERS + 1) * (L_LAYERS + 1)));
}

// ---------------------------------------------------------------------------
// Launch sequence: hist | scan1(+finals) | scan3(+order) | scatter+init |
// 3x fused SpMM | dot.   (8 launches)
// ---------------------------------------------------------------------------
extern "C" void kernel_launch(void* const* d_in, const int* in_sizes, int n_in,
                              void* d_out, int out_size)
{
    const float4* user_emb    = (const float4*)d_in[0];
    const float4* item_emb    = (const float4*)d_in[1];
    const float4* symptom_emb = (const float4*)d_in[2];
    const float4* herb_emb    = (const float4*)d_in[3];
    const float*  user_lw     = (const float*)d_in[4];
    const float*  item_lw     = (const float*)d_in[5];
    const float*  edge_val    = (const float*)d_in[6];
    const int*    edge_row    = (const int*)d_in[7];
    const int*    edge_col    = (const int*)d_in[8];
    const int*    users       = (const int*)d_in[9];
    const int*    items       = (const int*)d_in[10];

    int E = in_sizes[6];
    int B = in_sizes[9];

    const int TB = 256;
    int e4 = (E + 3) / 4;

    k_hist<<<(e4 + TB - 1) / TB, TB>>>(edge_row, E);
    k_scan1<<<SCAN_NB, SCAN_BLK>>>();
    k_scan3<<<(N_CNT + TB - 1) / TB, TB>>>();

    int si_threads = (e4 > NH4 ? e4 : NH4);
    k_scatter_init<<<(si_threads + TB - 1) / TB, TB>>>(
        edge_row, edge_col, edge_val, E,
        user_emb, item_emb, symptom_emb, herb_emb, user_lw, item_lw);

    int spmm_blocks = (N_CNT * 8 + TB - 1) / TB;
    for (int layer = 1; layer <= L_LAYERS; layer++) {
        k_spmm_fused<<<spmm_blocks, TB>>>(user_lw, item_lw, layer);
    }

    k_dot<<<(B * 8 + TB - 1) / TB, TB>>>(users, items, (float*)d_out, B);
}

// round 11
// speedup vs baseline: 1.2076x; 1.0608x over previous
#include <cuda_runtime.h>
#include <cuda_fp16.h>
#include <cuda_bf16.h>

// Problem constants (fixed by the reference).
#define U_CNT 100000
#define I_CNT 100000
#define N_CNT 200000           // U + I
#define L_LAYERS 3
#define ROW_F4 16              // D/4 float4 per node row (fp32 inputs)
#define ROW_H4 8               // 8 uint4 per node row (64 halves, 128B)
#define NH4   (N_CNT * ROW_H4) // 1.6M uint4 = 25.6 MB per layer buffer
#define E_MAX 6400000
#define SCAN_BLK 1024
#define SCAN_NB ((N_CNT + SCAN_BLK - 1) / SCAN_BLK)   // 196
#define DBINS 256
#define SPMM_U_BLOCKS ((U_CNT * 8 + 255) / 256)       // 3125

// val quantization: val in [0, 1/32), 14-bit fixed point in bits [18,32).
#define VAL_ENC_SCALE (32.0f * 16383.0f)
#define VAL_DEC_SCALE (1.0f / (32.0f * 16383.0f))

// Scratch (__device__ globals only — allocation-free rule).
// Steady-state invariants maintained across calls (zero-init by loader first):
//   g_deg  == 0 on entry (re-zeroed in k_scan3)
//   g_dbin == 0 on entry (re-zeroed in k_scatU_init — BOTH partitions)
//   g_tick == 0 on entry (re-zeroed by scan1's last block)
__device__ uint4    g_Lh[L_LAYERS + 1][NH4];   // 4 x 25.6 MB fp16 layer buffers
__device__ uint4    g_sem[NH4];                // fp16 semantic (symptom|herb) table
__device__ unsigned g_csr [E_MAX];             // packed (col | q<<18), grouped by row
__device__ int      g_deg [N_CNT];
__device__ int      g_ptr [N_CNT + 1];
__device__ int      g_cursor[N_CNT];
__device__ int      g_bsum[SCAN_NB];
__device__ int      g_dbin[2][DBINS];          // degree bins: [0]=users, [1]=items
__device__ int      g_order[N_CNT];            // users desc-deg in [0,U), items in [U,N)
__device__ int      g_tick;

__device__ __forceinline__ float sigm(float x) { return 1.0f / (1.0f + __expf(-x)); }

__device__ __forceinline__ uint4 pack8(const float* x)
{
    uint4 r;
    half2 h0 = __floats2half2_rn(x[0], x[1]);
    half2 h1 = __floats2half2_rn(x[2], x[3]);
    half2 h2 = __floats2half2_rn(x[4], x[5]);
    half2 h3 = __floats2half2_rn(x[6], x[7]);
    r.x = *(unsigned*)&h0; r.y = *(unsigned*)&h1;
    r.z = *(unsigned*)&h2; r.w = *(unsigned*)&h3;
    return r;
}

__device__ __forceinline__ void unpack8(uint4 q, float* x)
{
    half2* hp = (half2*)&q;
    float2 f0 = __half22float2(hp[0]);
    float2 f1 = __half22float2(hp[1]);
    float2 f2 = __half22float2(hp[2]);
    float2 f3 = __half22float2(hp[3]);
    x[0] = f0.x; x[1] = f0.y; x[2] = f1.x; x[3] = f1.y;
    x[4] = f2.x; x[5] = f2.y; x[6] = f3.x; x[7] = f3.y;
}

__device__ __forceinline__ void acc8(float* acc, uint4 q, float v)
{
    float x[8];
    unpack8(q, x);
    #pragma unroll
    for (int k = 0; k < 8; k++) acc[k] = fmaf(v, x[k], acc[k]);
}

// Shared SpMM row body: gather+accumulate row `rw` of `layer`, mix, store.
__device__ __forceinline__ void spmm_row_do(int layer, int rw, int sub,
                                            const float* __restrict__ ulw,
                                            const float* __restrict__ ilw)
{
    const uint4* __restrict__ src = g_Lh[layer - 1];
    uint4*       __restrict__ dst = g_Lh[layer];

    int start = __ldg(&g_ptr[rw]);
    int end   = __ldg(&g_ptr[rw + 1]);

    float acc[8];
    #pragma unroll
    for (int k = 0; k < 8; k++) acc[k] = 0.0f;

    int j = start;
    for (; j + 4 <= end; j += 4) {
        unsigned e0 = __ldg(&g_csr[j + 0]);
        unsigned e1 = __ldg(&g_csr[j + 1]);
        unsigned e2 = __ldg(&g_csr[j + 2]);
        unsigned e3 = __ldg(&g_csr[j + 3]);
        uint4 q0 = __ldg(&src[(e0 & 0x3FFFFu) * ROW_H4 + sub]);
        uint4 q1 = __ldg(&src[(e1 & 0x3FFFFu) * ROW_H4 + sub]);
        uint4 q2 = __ldg(&src[(e2 & 0x3FFFFu) * ROW_H4 + sub]);
        uint4 q3 = __ldg(&src[(e3 & 0x3FFFFu) * ROW_H4 + sub]);
        acc8(acc, q0, (float)(e0 >> 18) * VAL_DEC_SCALE);
        acc8(acc, q1, (float)(e1 >> 18) * VAL_DEC_SCALE);
        acc8(acc, q2, (float)(e2 >> 18) * VAL_DEC_SCALE);
        acc8(acc, q3, (float)(e3 >> 18) * VAL_DEC_SCALE);
    }
    for (; j < end; j++) {
        unsigned e0 = __ldg(&g_csr[j]);
        uint4 q0 = __ldg(&src[(e0 & 0x3FFFFu) * ROW_H4 + sub]);
        acc8(acc, q0, (float)(e0 >> 18) * VAL_DEC_SCALE);
    }

    float a = (rw < U_CNT) ? sigm(__ldg(ulw + layer)) : sigm(__ldg(ilw + layer));

    float o[8];
    unpack8(__ldg(&g_sem[rw * ROW_H4 + sub]), o);

    float x[8];
    #pragma unroll
    for (int k = 0; k < 8; k++) x[k] = a * acc[k] + (1.0f - a) * o[k];

    __stcs(&dst[rw * ROW_H4 + sub], pack8(x));
}

// ---------------------------------------------------------------------------
// Degree histogram: fire-and-forget REDG atomics, 4 edges/thread.
// ---------------------------------------------------------------------------
__global__ void k_hist(const int* __restrict__ row, int E)
{
    int i = blockIdx.x * blockDim.x + threadIdx.x;
    int e0 = i * 4;
    if (e0 + 3 < E) {
        int4 r4 = __ldg((const int4*)(row + e0));
        atomicAdd(&g_deg[r4.x], 1);
        atomicAdd(&g_deg[r4.y], 1);
        atomicAdd(&g_deg[r4.z], 1);
        atomicAdd(&g_deg[r4.w], 1);
    } else if (e0 < E) {
        for (int e = e0; e < E; e++) atomicAdd(&g_deg[__ldg(row + e)], 1);
    }
}

// ---------------------------------------------------------------------------
// Scan 1: warp-shuffle block scan of degrees + per-partition degree bins.
// Last finished block scans the 196 block sums AND both 256-entry bin sets.
// ---------------------------------------------------------------------------
__global__ void k_scan1()
{
    __shared__ int sw[32];
    __shared__ int sbuf[256];
    __shared__ int isLast;
    int i    = blockIdx.x * SCAN_BLK + threadIdx.x;
    int lane = threadIdx.x & 31;
    int wid  = threadIdx.x >> 5;

    int v = (i < N_CNT) ? g_deg[i] : 0;

    int x = v;
    #pragma unroll
    for (int off = 1; off < 32; off <<= 1) {
        int y = __shfl_up_sync(0xffffffffu, x, off);
        if (lane >= off) x += y;
    }
    if (lane == 31) sw[wid] = x;
    __syncthreads();

    if (wid == 0) {
        int wv = sw[lane];
        int wx = wv;
        #pragma unroll
        for (int off = 1; off < 32; off <<= 1) {
            int y = __shfl_up_sync(0xffffffffu, wx, off);
            if (lane >= off) wx += y;
        }
        sw[lane] = wx - wv;
    }
    __syncthreads();

    int incl = x + sw[wid];
    if (i < N_CNT) g_ptr[i] = incl - v;             // exclusive, block-local
    if (threadIdx.x == SCAN_BLK - 1) g_bsum[blockIdx.x] = incl;

    // per-partition degree-bin histogram (g_dbin == 0 on entry, invariant)
    if (i < N_CNT) {
        int d = v < DBINS ? v : DBINS - 1;
        atomicAdd(&g_dbin[i < U_CNT ? 0 : 1][d], 1);
    }

    __threadfence();
    if (threadIdx.x == 0)
        isLast = (atomicAdd(&g_tick, 1) == (int)gridDim.x - 1);
    __syncthreads();
    if (!isLast) return;

    int t = threadIdx.x;

    // exclusive scan of block sums (196 values)
    int v2 = (t < SCAN_NB) ? g_bsum[t] : 0;
    if (t < 256) sbuf[t] = v2;
    __syncthreads();
    for (int off = 1; off < 256; off <<= 1) {
        int u = (t < 256 && t >= off) ? sbuf[t - off] : 0;
        __syncthreads();
        if (t < 256) sbuf[t] += u;
        __syncthreads();
    }
    if (t < SCAN_NB) g_bsum[t] = sbuf[t] - v2;
    if (t == SCAN_NB - 1) g_ptr[N_CNT] = sbuf[t];
    __syncthreads();

    // exclusive scans of the two degree-bin sets
    #pragma unroll
    for (int part = 0; part < 2; part++) {
        int v3 = (t < DBINS) ? g_dbin[part][t] : 0;
        if (t < 256) sbuf[t] = v3;
        __syncthreads();
        for (int off = 1; off < 256; off <<= 1) {
            int u = (t < 256 && t >= off) ? sbuf[t - off] : 0;
            __syncthreads();
            if (t < 256) sbuf[t] += u;
            __syncthreads();
        }
        if (t < DBINS) g_dbin[part][t] = sbuf[t] - v3;
        __syncthreads();
    }

    if (t == 0) g_tick = 0;   // restore invariant
}

// ---------------------------------------------------------------------------
// Scan 3: finalize ptr/cursor; per-partition descending-degree counting sort
// (users -> g_order[0,U), items -> g_order[U,N)). Re-zero g_deg (invariant).
// ---------------------------------------------------------------------------
__global__ void k_scan3()
{
    int i = blockIdx.x * blockDim.x + threadIdx.x;
    if (i >= N_CNT) return;
    int p = g_ptr[i] + g_bsum[i / SCAN_BLK];
    g_ptr[i]    = p;
    g_cursor[i] = p;
    int d = g_deg[i];
    d = d < DBINS ? d : DBINS - 1;
    if (i < U_CNT) {
        int pos = atomicAdd(&g_dbin[0][d], 1);
        g_order[U_CNT - 1 - pos] = i;
    } else {
        int pos = atomicAdd(&g_dbin[1][d], 1);
        g_order[U_CNT + I_CNT - 1 - pos] = i;
    }
    g_deg[i] = 0;             // restore invariant
}

// ---------------------------------------------------------------------------
// FUSED user-edge scatter + init. Thread i:
//   (1) reserves+stores CSR slots for its edges with row < U_CNT,
//   (2) computes init element i (layer-0 mix + fp16 sem table) in the shadow
//       of the atomic round-trips.
// Also re-zeroes BOTH g_dbin partitions (512 ints, 2 per thread of block 0).
// ---------------------------------------------------------------------------
__global__ void k_scatU_init(const int*    __restrict__ row, const int* __restrict__ col,
                             const float*  __restrict__ val, int E,
                             const float4* __restrict__ ue, const float4* __restrict__ ie,
                             const float4* __restrict__ se, const float4* __restrict__ he,
                             const float*  __restrict__ ulw, const float* __restrict__ ilw)
{
    int i = blockIdx.x * blockDim.x + threadIdx.x;
    if (blockIdx.x == 0 && threadIdx.x < DBINS) {
        ((int*)g_dbin)[threadIdx.x]         = 0;   // user bins
        ((int*)g_dbin)[threadIdx.x + DBINS] = 0;   // item bins (R9 bug: was missed)
    }

    int e0 = i * 4;
    bool full = (e0 + 3 < E);
    int p[4], c[4];
    float v[4];
    bool m[4];
    if (full) {
        int4   r4 = __ldg((const int4*)(row + e0));
        int4   c4 = __ldg((const int4*)(col + e0));
        float4 v4 = __ldg((const float4*)(val + e0));
        int r[4] = { r4.x, r4.y, r4.z, r4.w };
        c[0] = c4.x; c[1] = c4.y; c[2] = c4.z; c[3] = c4.w;
        v[0] = v4.x; v[1] = v4.y; v[2] = v4.z; v[3] = v4.w;
        #pragma unroll
        for (int k = 0; k < 4; k++) {
            m[k] = (r[k] < U_CNT);
            p[k] = m[k] ? atomicAdd(&g_cursor[r[k]], 1) : 0;
        }
    }

    // init element (independent streaming work hides atomic latency)
    if (i < NH4) {
        int rw  = i >> 3;
        int sub = i & 7;

        const float4* base;
        const float4* sem;
        int r;
        float a;
        if (rw < U_CNT) { a = sigm(__ldg(ulw)); base = ue; sem = se; r = rw; }
        else            { a = sigm(__ldg(ilw)); base = ie; sem = he; r = rw - U_CNT; }

        float4 b0 = __ldcs(&base[r * ROW_F4 + sub * 2]);
        float4 b1 = __ldcs(&base[r * ROW_F4 + sub * 2 + 1]);
        float4 s0 = __ldcs(&sem [r * ROW_F4 + sub * 2]);
        float4 s1 = __ldcs(&sem [r * ROW_F4 + sub * 2 + 1]);

        float xs[8] = { s0.x, s0.y, s0.z, s0.w, s1.x, s1.y, s1.z, s1.w };
        float xb[8] = { b0.x, b0.y, b0.z, b0.w, b1.x, b1.y, b1.z, b1.w };
        float x[8];
        #pragma unroll
        for (int k = 0; k < 8; k++) x[k] = a * xb[k] + (1.0f - a) * xs[k];

        g_sem[i]   = pack8(xs);
        g_Lh[0][i] = pack8(x);
    }

    if (full) {
        #pragma unroll
        for (int k = 0; k < 4; k++) {
            if (m[k]) {
                int q = __float2int_rn(v[k] * VAL_ENC_SCALE);
                q = q < 16383 ? q : 16383;
                __stcs(&g_csr[p[k]], (unsigned)c[k] | ((unsigned)q << 18));
            }
        }
    } else if (e0 < E) {
        for (int e = e0; e < E; e++) {
            int r = __ldg(row + e);
            if (r >= U_CNT) continue;
            int pp = atomicAdd(&g_cursor[r], 1);
            int q = __float2int_rn(__ldg(val + e) * VAL_ENC_SCALE);
            q = q < 16383 ? q : 16383;
            __stcs(&g_csr[pp], (unsigned)__ldg(col + e) | ((unsigned)q << 18));
        }
    }
}

// ---------------------------------------------------------------------------
// FUSED: spmm layer-1 over USER rows  ∥  scatter of ITEM edges.
// Role by bid: bid%3==0 && bid/3 < SPMM_U_BLOCKS -> spmm; everything else ->
// scatter with sb = bid - min(ceil(bid/3), SPMM_U_BLOCKS)  (provably unique,
// sequential 0..).  CSR ranges disjoint: users [0, ptr[U]), items [ptr[U], E).
// ---------------------------------------------------------------------------
__global__ void k_spmmU1_scatI(const int*   __restrict__ row, const int* __restrict__ col,
                               const float* __restrict__ val, int E,
                               const float* __restrict__ ulw, const float* __restrict__ ilw)
{
    int bid = blockIdx.x;
    bool is_spmm = (bid % 3 == 0) && (bid / 3 < SPMM_U_BLOCKS);
    if (is_spmm) {
        int t = (bid / 3) * blockDim.x + threadIdx.x;
        int g = t >> 3;
        if (g >= U_CNT) return;
        int sub = t & 7;
        int rw = __ldg(&g_order[g]);           // user rows live in [0, U)
        spmm_row_do(1, rw, sub, ulw, ilw);
        return;
    }
    // #spmm blocks with index < bid (collision-free enumeration of the rest)
    int nsp = (bid + 2) / 3;
    if (nsp > SPMM_U_BLOCKS) nsp = SPMM_U_BLOCKS;
    int sb = bid - nsp;
    int i = sb * blockDim.x + threadIdx.x;

    int e0 = i * 4;
    if (e0 >= E) return;
    if (e0 + 3 < E) {
        int4   r4 = __ldg((const int4*)(row + e0));
        int4   c4 = __ldg((const int4*)(col + e0));
        float4 v4 = __ldg((const float4*)(val + e0));
        int r[4] = { r4.x, r4.y, r4.z, r4.w };
        int c[4] = { c4.x, c4.y, c4.z, c4.w };
        float v[4] = { v4.x, v4.y, v4.z, v4.w };
        int p[4];
        bool m[4];
        #pragma unroll
        for (int k = 0; k < 4; k++) {
            m[k] = (r[k] >= U_CNT);
            p[k] = m[k] ? atomicAdd(&g_cursor[r[k]], 1) : 0;
        }
        #pragma unroll
        for (int k = 0; k < 4; k++) {
            if (m[k]) {
                int q = __float2int_rn(v[k] * VAL_ENC_SCALE);
                q = q < 16383 ? q : 16383;
                __stcs(&g_csr[p[k]], (unsigned)c[k] | ((unsigned)q << 18));
            }
        }
    } else {
        for (int e = e0; e < E; e++) {
            int r = __ldg(row + e);
            if (r < U_CNT) continue;
            int pp = atomicAdd(&g_cursor[r], 1);
            int q = __float2int_rn(__ldg(val + e) * VAL_ENC_SCALE);
            q = q < 16383 ? q : 16383;
            __stcs(&g_csr[pp], (unsigned)__ldg(col + e) | ((unsigned)q << 18));
        }
    }
}

// ---------------------------------------------------------------------------
// SpMM layer-1 over ITEM rows only.
// ---------------------------------------------------------------------------
__global__ void k_spmmI1(const float* __restrict__ ulw, const float* __restrict__ ilw)
{
    int t = blockIdx.x * blockDim.x + threadIdx.x;
    int g = t >> 3;
    if (g >= I_CNT) return;
    int sub = t & 7;
    int rw = __ldg(&g_order[U_CNT + g]);
    spmm_row_do(1, rw, sub, ulw, ilw);
}

// ---------------------------------------------------------------------------
// Full SpMM (layers 2, 3) over all rows.
// ---------------------------------------------------------------------------
__global__ void k_spmm_fused(const float* __restrict__ ulw, const float* __restrict__ ilw,
                             int layer)
{
    int t = blockIdx.x * blockDim.x + threadIdx.x;
    int g = t >> 3;
    if (g >= N_CNT) return;
    int sub = t & 7;
    int rw = __ldg(&g_order[g]);
    spmm_row_do(layer, rw, sub, ulw, ilw);
}

// ---------------------------------------------------------------------------
// Final dot: 8 lanes per (user, item) pair; sum 4 layer rows in fp32.
// ---------------------------------------------------------------------------
__global__ void k_dot(const int* __restrict__ users, const int* __restrict__ items,
                      float* __restrict__ out, int B)
{
    int t = blockIdx.x * blockDim.x + threadIdx.x;
    int b = t >> 3;
    if (b >= B) return;
    int sub = t & 7;

    int u  = __ldg(users + b);
    int it = __ldg(items + b);

    float su[8], si[8];
    #pragma unroll
    for (int k = 0; k < 8; k++) { su[k] = 0.0f; si[k] = 0.0f; }

    #pragma unroll
    for (int l = 0; l <= L_LAYERS; l++) {
        float xu[8], xi[8];
        unpack8(__ldg(&g_Lh[l][u * ROW_H4 + sub]), xu);
        unpack8(__ldg(&g_Lh[l][(U_CNT + it) * ROW_H4 + sub]), xi);
        #pragma unroll
        for (int k = 0; k < 8; k++) { su[k] += xu[k]; si[k] += xi[k]; }
    }

    float s = 0.0f;
    #pragma unroll
    for (int k = 0; k < 8; k++) s = fmaf(su[k], si[k], s);

    s += __shfl_down_sync(0xffffffffu, s, 4, 8);
    s += __shfl_down_sync(0xffffffffu, s, 2, 8);
    s += __shfl_down_sync(0xffffffffu, s, 1, 8);

    if (sub == 0) out[b] = s * (1.0f / ((L_LAYERS + 1) * (L_LAYERS + 1)));
}

// ---------------------------------------------------------------------------
// Launch sequence: hist | scan1 | scan3 | scatU+init | spmmU1∥scatI |
// spmmI1 | spmm2 | spmm3 | dot.
// ---------------------------------------------------------------------------
extern "C" void kernel_launch(void* const* d_in, const int* in_sizes, int n_in,
                              void* d_out, int out_size)
{
    const float4* user_emb    = (const float4*)d_in[0];
    const float4* item_emb    = (const float4*)d_in[1];
    const float4* symptom_emb = (const float4*)d_in[2];
    const float4* herb_emb    = (const float4*)d_in[3];
    const float*  user_lw     = (const float*)d_in[4];
    const float*  item_lw     = (const float*)d_in[5];
    const float*  edge_val    = (const float*)d_in[6];
    const int*    edge_row    = (const int*)d_in[7];
    const int*    edge_col    = (const int*)d_in[8];
    const int*    users       = (const int*)d_in[9];
    const int*    items       = (const int*)d_in[10];

    int E = in_sizes[6];
    int B = in_sizes[9];

    const int TB = 256;
    int e4 = (E + 3) / 4;

    k_hist<<<(e4 + TB - 1) / TB, TB>>>(edge_row, E);
    k_scan1<<<SCAN_NB, SCAN_BLK>>>();
    k_scan3<<<(N_CNT + TB - 1) / TB, TB>>>();

    int si_threads = (e4 > NH4 ? e4 : NH4);
    k_scatU_init<<<(si_threads + TB - 1) / TB, TB>>>(
        edge_row, edge_col, edge_val, E,
        user_emb, item_emb, symptom_emb, herb_emb, user_lw, item_lw);

    // k5 grid: enough blocks that spmm indices cover SPMM_U_BLOCKS and
    // scatter indices cover scat_blocks. With the nsp-based mapping, block
    // bid's scatter index is bid - min(ceil(bid/3), SPMM_U_BLOCKS), which is
    // nondecreasing and hits every integer; need largest sb = scat_blocks-1.
    int scat_blocks = (e4 + TB - 1) / TB;
    int k5_blocks = SPMM_U_BLOCKS + scat_blocks;          // exact cover
    int need_for_spmm = (SPMM_U_BLOCKS - 1) * 3 + 1;
    if (k5_blocks < need_for_spmm) k5_blocks = need_for_spmm;
    k_spmmU1_scatI<<<k5_blocks, TB>>>(edge_row, edge_col, edge_val, E,
                                      user_lw, item_lw);

    k_spmmI1<<<(I_CNT * 8 + TB - 1) / TB, TB>>>(user_lw, item_lw);

    int spmm_blocks = (N_CNT * 8 + TB - 1) / TB;
    for (int layer = 2; layer <= L_LAYERS; layer++) {
        k_spmm_fused<<<spmm_blocks, TB>>>(user_lw, item_lw, layer);
    }

    k_dot<<<(B * 8 + TB - 1) / TB, TB>>>(users, items, (float*)d_out, B);
}